// round 14
// baseline (speedup 1.0000x reference)
#include <cuda_runtime.h>
#include <cuda_bf16.h>
#include <cuda_fp16.h>
#include <cstdint>

#define NB 8
#define NS 4096
#define NE 8
#define NROWS (NB * NS)
#define TILE 256            // keys per smem tile (triple-buffered)

// Packed operand buffers (fragment-order layouts, all f16):
//  g_K[row][4 w]: w_m = (k_{2m}, k_{2m+1}) f16x2
//  g_V2[pair][8 w]: w_e = {lo16 = f16 v_{2p,e}, hi16 = f16 v_{2p+1,e}}
__device__ __align__(16) uint32_t g_K[NROWS * 4];
__device__ __align__(16) uint32_t g_V2[(NROWS / 2) * 8];

__device__ __forceinline__ float ex2f(float x) {
    float y; asm("ex2.approx.ftz.f32 %0, %1;" : "=f"(y) : "f"(x)); return y;
}
// f16x2 {lo, hi}
__device__ __forceinline__ uint32_t cvt2h(float lo, float hi) {
    uint32_t d; asm("cvt.rn.f16x2.f32 %0, %2, %1;" : "=r"(d) : "f"(lo), "f"(hi)); return d;
}
__device__ __forceinline__ void mma1688f16(
    float& d0, float& d1, float& d2, float& d3,
    uint32_t a0, uint32_t a1, uint32_t b0,
    float c0, float c1, float c2, float c3)
{
    asm("mma.sync.aligned.m16n8k8.row.col.f32.f16.f16.f32 "
        "{%0,%1,%2,%3},{%4,%5},{%6},{%7,%8,%9,%10};"
        : "=f"(d0), "=f"(d1), "=f"(d2), "=f"(d3)
        : "r"(a0), "r"(a1), "r"(b0),
          "f"(c0), "f"(c1), "f"(c2), "f"(c3));
}
__device__ __forceinline__ void mma16816f16(
    float& d0, float& d1, float& d2, float& d3,
    uint32_t a0, uint32_t a1, uint32_t a2, uint32_t a3,
    uint32_t b0, uint32_t b1,
    float c0, float c1, float c2, float c3)
{
    asm("mma.sync.aligned.m16n8k16.row.col.f32.f16.f16.f32 "
        "{%0,%1,%2,%3},{%4,%5,%6,%7},{%8,%9},{%10,%11,%12,%13};"
        : "=f"(d0), "=f"(d1), "=f"(d2), "=f"(d3)
        : "r"(a0), "r"(a1), "r"(a2), "r"(a3), "r"(b0), "r"(b1),
          "f"(c0), "f"(c1), "f"(c2), "f"(c3));
}
__device__ __forceinline__ void cpasync16(uint32_t smem_addr, const void* gptr) {
    asm volatile("cp.async.ca.shared.global [%0], [%1], 16;"
                 :: "r"(smem_addr), "l"(gptr));
}
__device__ __forceinline__ void cpcommit() {
    asm volatile("cp.async.commit_group;");
}
template<int N>
__device__ __forceinline__ void cpwait() {
    asm volatile("cp.async.wait_group %0;" :: "n"(N));
}

// ---------------------------------------------------------------------------
// Kernel 1: K/V projection + cos; 4 threads per row (2 output dims each)
// for latency hiding (kv was latency-bound at 2 threads/row: issue 15%).
// ---------------------------------------------------------------------------
__global__ void __launch_bounds__(256) kv_kernel(
    const float* __restrict__ x,
    const float* __restrict__ Wk, const float* __restrict__ bk,
    const float* __restrict__ Wv, const float* __restrict__ bv,
    const float* __restrict__ theta)
{
    __shared__ float sWk[64], sWv[64];
    __shared__ float sbk[8], sbv[8], sth[8];
    int tid = threadIdx.x;
    if (tid < 64) { sWk[tid] = Wk[tid]; sWv[tid] = Wv[tid]; }
    if (tid < 8)  { sbk[tid] = bk[tid]; sbv[tid] = bv[tid]; sth[tid] = theta[tid]; }
    __syncthreads();

    int t = blockIdx.x * blockDim.x + tid;        // 0 .. 4*NROWS-1
    int r = t >> 2, qq = t & 3, jb = qq * 2;      // this thread: dims jb, jb+1

    const float4* xp = (const float4*)(x + (size_t)r * 8);
    float4 xa = xp[0], xb = xp[1];
    float xr[8] = {xa.x, xa.y, xa.z, xa.w, xb.x, xb.y, xb.z, xb.w};

    float ko[2];
    unsigned short vh[2];
#pragma unroll
    for (int jj = 0; jj < 2; jj++) {
        int j = jb + jj;
        float hk = sbk[j], hv = sbv[j];
#pragma unroll
        for (int i = 0; i < 8; i++) {
            hk = fmaf(xr[i], sWk[j * 8 + i], hk);
            hv = fmaf(xr[i], sWv[j * 8 + i], hv);
        }
        float th = sth[j];
        ko[jj] = __cosf(hk + th);
        float vv = __cosf(hv + th);
        __half hv16 = __float2half_rn(vv);
        vh[jj] = *(unsigned short*)&hv16;
    }
    // K word qq = (k_{2qq}, k_{2qq+1}) — exactly this thread's two dims
    g_K[(size_t)r * 4 + qq] = cvt2h(ko[0], ko[1]);
    // V f16 pair-interleaved: lo16 = even row
    unsigned short* vb = (unsigned short*)(g_V2 + (size_t)(r >> 1) * 8);
    int rp = r & 1;
    vb[jb * 2 + rp]       = vh[0];
    vb[(jb + 1) * 2 + rp] = vh[1];
}

// ---------------------------------------------------------------------------
// Kernel 2: FA2-style attention (round-12 proven core, byte-identical).
// Q projected in-prologue (overlapped with tile-0 cp.async), f16 m16n8k8
// score MMAs, 8x f32 ex2, f16 P·V MMA, l via ones-MMA, triple-buffered
// cp.async K/V ring (single barrier/tile), fused normalize + Wc epilogue.
// No max-subtraction (|score*log2e| <= 5.8).
// ---------------------------------------------------------------------------
__global__ void __launch_bounds__(128, 4) attn_kernel(
    const float* __restrict__ x,
    const float* __restrict__ Wq, const float* __restrict__ bq,
    const float* __restrict__ theta,
    const float* __restrict__ Wc, const float* __restrict__ bc,
    float* __restrict__ out)
{
    __shared__ uint32_t sK[3][TILE * 4];      // 4 KB per buffer
    __shared__ uint32_t sV[3][TILE * 4];      // 4 KB per buffer
    __shared__ uint32_t sQ[64 * 4];           // 1 KB: per-CTA Q fragments
    __shared__ float sEp[512];                // 2 KB: epilogue scratch
    __shared__ float sWc[64], sbc[8];

    int tid = threadIdx.x;
    int warp = tid >> 5, lane = tid & 31;
    int g = lane >> 2, m = lane & 3;
    int b = blockIdx.y;
    int qbase = blockIdx.x * 64 + warp * 16;

    if (tid < 64) sWc[tid] = Wc[tid];
    if (tid < 8)  sbc[tid] = bc[tid];

    const uint4* Kg = (const uint4*)(g_K  + (size_t)b * NS * 4);
    const uint4* Vg = (const uint4*)(g_V2 + (size_t)b * (NS / 2) * 8);
    const int NT = NS / TILE;                 // 16 tiles
    const int U4 = TILE;                      // 256 uint4 per array per tile

    // issue tile 0 (2 uint4 per thread per array)
#pragma unroll
    for (int i = 0; i < 2; i++) {
        int idx = i * 128 + tid;
        cpasync16((uint32_t)__cvta_generic_to_shared(&((uint4*)sK[0])[idx]), Kg + idx);
        cpasync16((uint32_t)__cvta_generic_to_shared(&((uint4*)sV[0])[idx]), Vg + idx);
    }
    cpcommit();

    // ---- Q prologue (overlaps tile-0 cp.async): 128 threads = 64 rows x 2 halves
    {
        const float QS = 0.5f * 1.4426950408889634f;  // SCALE * log2(e)
        int qrow = tid >> 1, qhalf = tid & 1, jb = qhalf * 4;
        int grow = b * NS + blockIdx.x * 64 + qrow;
        const float4* xp = (const float4*)(x + (size_t)grow * 8);
        float4 xa = xp[0], xb = xp[1];
        float xr[8] = {xa.x, xa.y, xa.z, xa.w, xb.x, xb.y, xb.z, xb.w};
        float qo[4];
#pragma unroll
        for (int jj = 0; jj < 4; jj++) {
            int j = jb + jj;
            float acc = __ldg(&bq[j]);
#pragma unroll
            for (int i = 0; i < 8; i++)
                acc = fmaf(xr[i], __ldg(&Wq[j * 8 + i]), acc);
            qo[jj] = __cosf(acc + __ldg(&theta[j])) * QS;
        }
        sQ[qrow * 4 + qhalf * 2]     = cvt2h(qo[0], qo[1]);
        sQ[qrow * 4 + qhalf * 2 + 1] = cvt2h(qo[2], qo[3]);
    }
    __syncthreads();
    uint32_t qa0 = sQ[(warp * 16 + g) * 4 + m];       // row g,   e 2m,2m+1
    uint32_t qa1 = sQ[(warp * 16 + 8 + g) * 4 + m];   // row g+8

    float o0 = 0.f, o1 = 0.f, o2 = 0.f, o3 = 0.f;
    float la0 = 0.f, la1 = 0.f, la2 = 0.f, la3 = 0.f;
    const uint32_t ONE2 = 0x3C003C00u;        // f16x2 {1.0, 1.0}

    for (int t = 0; t < NT; t++) {
        int cur = t % 3;
        if (t + 1 < NT) {
            int nxt = (t + 1) % 3;
#pragma unroll
            for (int i = 0; i < 2; i++) {
                int idx = i * 128 + tid;
                cpasync16((uint32_t)__cvta_generic_to_shared(&((uint4*)sK[nxt])[idx]),
                          Kg + (t + 1) * U4 + idx);
                cpasync16((uint32_t)__cvta_generic_to_shared(&((uint4*)sV[nxt])[idx]),
                          Vg + (t + 1) * U4 + idx);
            }
            cpcommit();
            cpwait<1>();
        } else {
            cpwait<0>();
        }
        __syncthreads();   // data visible; also proves all warps left tile t-1

        const uint32_t* K = sK[cur];
        const uint32_t* V = sV[cur];
#pragma unroll 4
        for (int kt = 0; kt < TILE; kt += 16) {
            uint32_t kb0 = K[(kt + g) * 4 + m];       // key kt+g,   e 2m,2m+1
            uint32_t kb1 = K[(kt + 8 + g) * 4 + m];   // key kt+8+g
            float s0, s1, s2, s3, u0, u1, u2, u3;
            mma1688f16(s0, s1, s2, s3, qa0, qa1, kb0, 0.f, 0.f, 0.f, 0.f);
            mma1688f16(u0, u1, u2, u3, qa0, qa1, kb1, 0.f, 0.f, 0.f, 0.f);
            float p0 = ex2f(s0), p1 = ex2f(s1), p2 = ex2f(s2), p3 = ex2f(s3);
            float r0 = ex2f(u0), r1 = ex2f(u1), r2 = ex2f(u2), r3 = ex2f(u3);
            uint32_t pa0 = cvt2h(p0, p1), pa1 = cvt2h(p2, p3);
            uint32_t pa2 = cvt2h(r0, r1), pa3 = cvt2h(r2, r3);
            uint32_t vb0 = V[((kt >> 1) + m) * 8 + g];
            uint32_t vb1 = V[((kt >> 1) + 4 + m) * 8 + g];
            mma16816f16(o0, o1, o2, o3, pa0, pa1, pa2, pa3, vb0, vb1, o0, o1, o2, o3);
            mma16816f16(la0, la1, la2, la3, pa0, pa1, pa2, pa3, ONE2, ONE2,
                        la0, la1, la2, la3);
        }
        // no trailing barrier: 3-buffer ring + next leading barrier covers reuse
    }

    // Epilogue: la0 = l(row g), la2 = l(row g+8) (ones-MMA: all cols equal).
    float invg = 1.0f / la0;
    float invh = 1.0f / la2;
    float* ep = sEp + warp * 128;             // private per warp
    ep[g * 8 + 2 * m]           = o0 * invg;
    ep[g * 8 + 2 * m + 1]       = o1 * invg;
    ep[(g + 8) * 8 + 2 * m]     = o2 * invh;
    ep[(g + 8) * 8 + 2 * m + 1] = o3 * invh;
    __syncwarp();
    if (lane < 16) {
        const float4* rp = (const float4*)(ep + lane * 8);
        float4 va = rp[0], vbv = rp[1];
        float ov[8] = {va.x, va.y, va.z, va.w, vbv.x, vbv.y, vbv.z, vbv.w};
        float res[8];
#pragma unroll
        for (int j = 0; j < 8; j++) {
            float s = sbc[j];
#pragma unroll
            for (int e = 0; e < 8; e++)
                s = fmaf(ov[e], sWc[j * 8 + e], s);
            res[j] = s;
        }
        float4* op = (float4*)(out + ((size_t)b * NS + qbase + lane) * 8);
        op[0] = make_float4(res[0], res[1], res[2], res[3]);
        op[1] = make_float4(res[4], res[5], res[6], res[7]);
    }
}

// ---------------------------------------------------------------------------
extern "C" void kernel_launch(void* const* d_in, const int* in_sizes, int n_in,
                              void* d_out, int out_size)
{
    const float* x     = (const float*)d_in[0];
    const float* Wq    = (const float*)d_in[1];
    const float* bq    = (const float*)d_in[2];
    const float* Wk    = (const float*)d_in[3];
    const float* bk    = (const float*)d_in[4];
    const float* Wv    = (const float*)d_in[5];
    const float* bv    = (const float*)d_in[6];
    const float* theta = (const float*)d_in[7];
    const float* Wc    = (const float*)d_in[8];
    const float* bc    = (const float*)d_in[9];

    kv_kernel<<<(4 * NROWS) / 256, 256>>>(x, Wk, bk, Wv, bv, theta);

    dim3 grid(NS / 64, NB);                 // (64, 8) = 512 CTAs, 4 warps each
    attn_kernel<<<grid, 128>>>(x, Wq, bq, theta, Wc, bc, (float*)d_out);
}

// round 15
// speedup vs baseline: 1.1290x; 1.1290x over previous
#include <cuda_runtime.h>
#include <cuda_bf16.h>
#include <cuda_fp16.h>
#include <cstdint>

#define NB 8
#define NS 4096
#define NE 8
#define NROWS (NB * NS)
#define TILE 256            // keys per smem tile (triple-buffered)
#define KSPLIT 2

// Packed operand buffers (fragment-order layouts, all f16):
//  g_K[row][4 w]: w_m = (k_{2m}, k_{2m+1}) f16x2
//  g_V2[pair][8 w]: w_e = {lo16 = f16 v_{2p,e}, hi16 = f16 v_{2p+1,e}}
__device__ __align__(16) uint32_t g_K[NROWS * 4];
__device__ __align__(16) uint32_t g_V2[(NROWS / 2) * 8];
// Partials per key-split half: [z][row][12] = unnormalized o[8], l
__device__ __align__(16) float g_part[KSPLIT * NROWS * 12];

__device__ __forceinline__ float ex2f(float x) {
    float y; asm("ex2.approx.ftz.f32 %0, %1;" : "=f"(y) : "f"(x)); return y;
}
// f16x2 {lo, hi}
__device__ __forceinline__ uint32_t cvt2h(float lo, float hi) {
    uint32_t d; asm("cvt.rn.f16x2.f32 %0, %2, %1;" : "=r"(d) : "f"(lo), "f"(hi)); return d;
}
__device__ __forceinline__ void mma1688f16(
    float& d0, float& d1, float& d2, float& d3,
    uint32_t a0, uint32_t a1, uint32_t b0,
    float c0, float c1, float c2, float c3)
{
    asm("mma.sync.aligned.m16n8k8.row.col.f32.f16.f16.f32 "
        "{%0,%1,%2,%3},{%4,%5},{%6},{%7,%8,%9,%10};"
        : "=f"(d0), "=f"(d1), "=f"(d2), "=f"(d3)
        : "r"(a0), "r"(a1), "r"(b0),
          "f"(c0), "f"(c1), "f"(c2), "f"(c3));
}
__device__ __forceinline__ void mma16816f16(
    float& d0, float& d1, float& d2, float& d3,
    uint32_t a0, uint32_t a1, uint32_t a2, uint32_t a3,
    uint32_t b0, uint32_t b1,
    float c0, float c1, float c2, float c3)
{
    asm("mma.sync.aligned.m16n8k16.row.col.f32.f16.f16.f32 "
        "{%0,%1,%2,%3},{%4,%5,%6,%7},{%8,%9},{%10,%11,%12,%13};"
        : "=f"(d0), "=f"(d1), "=f"(d2), "=f"(d3)
        : "r"(a0), "r"(a1), "r"(a2), "r"(a3), "r"(b0), "r"(b1),
          "f"(c0), "f"(c1), "f"(c2), "f"(c3));
}
__device__ __forceinline__ void cpasync16(uint32_t smem_addr, const void* gptr) {
    asm volatile("cp.async.ca.shared.global [%0], [%1], 16;"
                 :: "r"(smem_addr), "l"(gptr));
}
__device__ __forceinline__ void cpcommit() {
    asm volatile("cp.async.commit_group;");
}
template<int N>
__device__ __forceinline__ void cpwait() {
    asm volatile("cp.async.wait_group %0;" :: "n"(N));
}

// ---------------------------------------------------------------------------
// Kernel 1: K/V projection + cos; 2 threads per row (R12-proven form).
// ---------------------------------------------------------------------------
__global__ void __launch_bounds__(256) kv_kernel(
    const float* __restrict__ x,
    const float* __restrict__ Wk, const float* __restrict__ bk,
    const float* __restrict__ Wv, const float* __restrict__ bv,
    const float* __restrict__ theta)
{
    __shared__ float sWk[64], sWv[64];
    __shared__ float sbk[8], sbv[8], sth[8];
    int tid = threadIdx.x;
    if (tid < 64) { sWk[tid] = Wk[tid]; sWv[tid] = Wv[tid]; }
    if (tid < 8)  { sbk[tid] = bk[tid]; sbv[tid] = bv[tid]; sth[tid] = theta[tid]; }
    __syncthreads();

    int t = blockIdx.x * blockDim.x + tid;
    int r = t >> 1, half = t & 1, jb = half * 4;

    const float4* xp = (const float4*)(x + (size_t)r * 8);
    float4 xa = xp[0], xb = xp[1];
    float xr[8] = {xa.x, xa.y, xa.z, xa.w, xb.x, xb.y, xb.z, xb.w};

    float ko[4];
    unsigned short vh[4];
#pragma unroll
    for (int jj = 0; jj < 4; jj++) {
        int j = jb + jj;
        float hk = sbk[j], hv = sbv[j];
#pragma unroll
        for (int i = 0; i < 8; i++) {
            hk = fmaf(xr[i], sWk[j * 8 + i], hk);
            hv = fmaf(xr[i], sWv[j * 8 + i], hv);
        }
        float th = sth[j];
        ko[jj] = __cosf(hk + th);
        float vv = __cosf(hv + th);
        __half hv16 = __float2half_rn(vv);
        vh[jj] = *(unsigned short*)&hv16;
    }
    uint2* Kd = (uint2*)(g_K + (size_t)r * 4 + half * 2);
    *Kd = make_uint2(cvt2h(ko[0], ko[1]), cvt2h(ko[2], ko[3]));
    unsigned short* vb = (unsigned short*)(g_V2 + (size_t)(r >> 1) * 8);
    int rp = r & 1;
#pragma unroll
    for (int jj = 0; jj < 4; jj++)
        vb[(jb + jj) * 2 + rp] = vh[jj];
}

// ---------------------------------------------------------------------------
// Kernel 2: FA2-style attention (R12 mainloop, pure 8x f32 ex2), key-split
// over blockIdx.z to flatten SMSP warp quantization (4096 warps x 128 steps).
// Writes unnormalized partials (o[8], l) to g_part.
// ---------------------------------------------------------------------------
__global__ void __launch_bounds__(128, 4) attn_kernel(
    const float* __restrict__ x,
    const float* __restrict__ Wq, const float* __restrict__ bq,
    const float* __restrict__ theta)
{
    __shared__ uint32_t sK[3][TILE * 4];      // 4 KB per buffer
    __shared__ uint32_t sV[3][TILE * 4];
    __shared__ uint32_t sQ[64 * 4];           // 1 KB
    __shared__ float sEp[512];                // 2 KB epilogue scratch
    __shared__ float sL[4][16];

    int tid = threadIdx.x;
    int warp = tid >> 5, lane = tid & 31;
    int g = lane >> 2, m = lane & 3;
    int b = blockIdx.y;
    int z = blockIdx.z;
    int qbase = blockIdx.x * 64 + warp * 16;

    const uint4* Kg = (const uint4*)(g_K  + (size_t)b * NS * 4) + (size_t)z * (NS / 2);
    const uint4* Vg = (const uint4*)(g_V2 + (size_t)b * (NS / 2) * 8) + (size_t)z * (NS / 2);
    const int NT = (NS / KSPLIT) / TILE;      // 8 tiles
    const int U4 = TILE;                      // 256 uint4 per array per tile

    // issue tile 0 (2 uint4 per thread per array)
#pragma unroll
    for (int i = 0; i < 2; i++) {
        int idx = i * 128 + tid;
        cpasync16((uint32_t)__cvta_generic_to_shared(&((uint4*)sK[0])[idx]), Kg + idx);
        cpasync16((uint32_t)__cvta_generic_to_shared(&((uint4*)sV[0])[idx]), Vg + idx);
    }
    cpcommit();

    // ---- Q prologue (overlaps tile-0 cp.async): 128 threads = 64 rows x 2 halves
    {
        const float QS = 0.5f * 1.4426950408889634f;  // SCALE * log2(e)
        int qrow = tid >> 1, qhalf = tid & 1, jb = qhalf * 4;
        int grow = b * NS + blockIdx.x * 64 + qrow;
        const float4* xp = (const float4*)(x + (size_t)grow * 8);
        float4 xa = xp[0], xb = xp[1];
        float xr[8] = {xa.x, xa.y, xa.z, xa.w, xb.x, xb.y, xb.z, xb.w};
        float qo[4];
#pragma unroll
        for (int jj = 0; jj < 4; jj++) {
            int j = jb + jj;
            float acc = __ldg(&bq[j]);
#pragma unroll
            for (int i = 0; i < 8; i++)
                acc = fmaf(xr[i], __ldg(&Wq[j * 8 + i]), acc);
            qo[jj] = __cosf(acc + __ldg(&theta[j])) * QS;
        }
        sQ[qrow * 4 + qhalf * 2]     = cvt2h(qo[0], qo[1]);
        sQ[qrow * 4 + qhalf * 2 + 1] = cvt2h(qo[2], qo[3]);
    }
    __syncthreads();
    uint32_t qa0 = sQ[(warp * 16 + g) * 4 + m];
    uint32_t qa1 = sQ[(warp * 16 + 8 + g) * 4 + m];

    float o0 = 0.f, o1 = 0.f, o2 = 0.f, o3 = 0.f;
    float la0 = 0.f, la1 = 0.f, la2 = 0.f, la3 = 0.f;
    const uint32_t ONE2 = 0x3C003C00u;        // f16x2 {1.0, 1.0}

    for (int t = 0; t < NT; t++) {
        int cur = t % 3;
        if (t + 1 < NT) {
            int nxt = (t + 1) % 3;
#pragma unroll
            for (int i = 0; i < 2; i++) {
                int idx = i * 128 + tid;
                cpasync16((uint32_t)__cvta_generic_to_shared(&((uint4*)sK[nxt])[idx]),
                          Kg + (t + 1) * U4 + idx);
                cpasync16((uint32_t)__cvta_generic_to_shared(&((uint4*)sV[nxt])[idx]),
                          Vg + (t + 1) * U4 + idx);
            }
            cpcommit();
            cpwait<1>();
        } else {
            cpwait<0>();
        }
        __syncthreads();   // data visible; also proves all warps left tile t-1

        const uint32_t* K = sK[cur];
        const uint32_t* V = sV[cur];
#pragma unroll 4
        for (int kt = 0; kt < TILE; kt += 16) {
            uint32_t kb0 = K[(kt + g) * 4 + m];
            uint32_t kb1 = K[(kt + 8 + g) * 4 + m];
            float s0, s1, s2, s3, u0, u1, u2, u3;
            mma1688f16(s0, s1, s2, s3, qa0, qa1, kb0, 0.f, 0.f, 0.f, 0.f);
            mma1688f16(u0, u1, u2, u3, qa0, qa1, kb1, 0.f, 0.f, 0.f, 0.f);
            float p0 = ex2f(s0), p1 = ex2f(s1), p2 = ex2f(s2), p3 = ex2f(s3);
            float r0 = ex2f(u0), r1 = ex2f(u1), r2 = ex2f(u2), r3 = ex2f(u3);
            uint32_t pa0 = cvt2h(p0, p1), pa1 = cvt2h(p2, p3);
            uint32_t pa2 = cvt2h(r0, r1), pa3 = cvt2h(r2, r3);
            uint32_t vb0 = V[((kt >> 1) + m) * 8 + g];
            uint32_t vb1 = V[((kt >> 1) + 4 + m) * 8 + g];
            mma16816f16(o0, o1, o2, o3, pa0, pa1, pa2, pa3, vb0, vb1, o0, o1, o2, o3);
            mma16816f16(la0, la1, la2, la3, pa0, pa1, pa2, pa3, ONE2, ONE2,
                        la0, la1, la2, la3);
        }
        // no trailing barrier: 3-buffer ring + next leading barrier covers reuse
    }

    // Epilogue: per-warp transpose of unnormalized o; write partials.
    float* ep = sEp + warp * 128;
    ep[g * 8 + 2 * m]           = o0;
    ep[g * 8 + 2 * m + 1]       = o1;
    ep[(g + 8) * 8 + 2 * m]     = o2;
    ep[(g + 8) * 8 + 2 * m + 1] = o3;
    if (m == 0) { sL[warp][g] = la0; sL[warp][8 + g] = la2; }
    __syncwarp();
    if (lane < 16) {
        const float4* rp = (const float4*)(ep + lane * 8);
        float4 va = rp[0], vbv = rp[1];
        int row = b * NS + qbase + lane;
        float* pp = g_part + ((size_t)z * NROWS + row) * 12;
        ((float4*)pp)[0] = va;
        ((float4*)pp)[1] = vbv;
        pp[8] = sL[warp][lane];
    }
}

// ---------------------------------------------------------------------------
// Kernel 3: combine key-split partials, normalize, fused Wc projection.
// ---------------------------------------------------------------------------
__global__ void __launch_bounds__(256) combine_kernel(
    const float* __restrict__ Wc, const float* __restrict__ bc,
    float* __restrict__ out)
{
    __shared__ float sWc[64], sbc[8];
    int tid = threadIdx.x;
    if (tid < 64) sWc[tid] = Wc[tid];
    if (tid < 8)  sbc[tid] = bc[tid];
    __syncthreads();

    int r = blockIdx.x * blockDim.x + tid;
    const float* p0 = g_part + (size_t)r * 12;
    const float* p1 = g_part + ((size_t)NROWS + r) * 12;
    float4 a0 = ((const float4*)p0)[0], a1 = ((const float4*)p0)[1];
    float4 b0 = ((const float4*)p1)[0], b1 = ((const float4*)p1)[1];
    float l = p0[8] + p1[8];
    float inv = 1.0f / l;
    float o[8] = {(a0.x + b0.x) * inv, (a0.y + b0.y) * inv,
                  (a0.z + b0.z) * inv, (a0.w + b0.w) * inv,
                  (a1.x + b1.x) * inv, (a1.y + b1.y) * inv,
                  (a1.z + b1.z) * inv, (a1.w + b1.w) * inv};
    float res[8];
#pragma unroll
    for (int j = 0; j < 8; j++) {
        float s = sbc[j];
#pragma unroll
        for (int e = 0; e < 8; e++)
            s = fmaf(o[e], sWc[j * 8 + e], s);
        res[j] = s;
    }
    float4* op = (float4*)(out + (size_t)r * 8);
    op[0] = make_float4(res[0], res[1], res[2], res[3]);
    op[1] = make_float4(res[4], res[5], res[6], res[7]);
}

// ---------------------------------------------------------------------------
extern "C" void kernel_launch(void* const* d_in, const int* in_sizes, int n_in,
                              void* d_out, int out_size)
{
    const float* x     = (const float*)d_in[0];
    const float* Wq    = (const float*)d_in[1];
    const float* bq    = (const float*)d_in[2];
    const float* Wk    = (const float*)d_in[3];
    const float* bk    = (const float*)d_in[4];
    const float* Wv    = (const float*)d_in[5];
    const float* bv    = (const float*)d_in[6];
    const float* theta = (const float*)d_in[7];
    const float* Wc    = (const float*)d_in[8];
    const float* bc    = (const float*)d_in[9];

    kv_kernel<<<(2 * NROWS) / 256, 256>>>(x, Wk, bk, Wv, bv, theta);

    dim3 grid(NS / 64, NB, KSPLIT);         // (64, 8, 2) = 1024 CTAs
    attn_kernel<<<grid, 128>>>(x, Wq, bq, theta);

    combine_kernel<<<NROWS / 256, 256>>>(Wc, bc, (float*)d_out);
}